// round 2
// baseline (speedup 1.0000x reference)
#include <cuda_runtime.h>
#include <math.h>

#define EPS 1e-5f

// Scratch (device globals — allowed; no runtime allocation)
__device__ float g_bufA[(size_t)64*192*56*56];   // 154 MB: conv1 out, region1 in-place
__device__ float g_bufB[(size_t)64*192*28*28];   // 38.5 MB: conv2 out, region2 in-place

__device__ __forceinline__ float gelu_exact(float x) {
    return 0.5f * x * (1.0f + erff(x * 0.70710678118654752f));
}

// ---------------------------------------------------------------------------
// conv1: x(64,3,224,224) * w(192,3,4,4) stride4 VALID -> bn -> gelu -> bufA(64,192,56,56)
// block = (oh, b), 192 threads = c_out. Non-overlapping 4x4 patches.
// ---------------------------------------------------------------------------
__global__ __launch_bounds__(192) void conv1_kernel(
    const float* __restrict__ x, const float* __restrict__ w,
    const float* __restrict__ bg, const float* __restrict__ bb,
    const float* __restrict__ bm, const float* __restrict__ bv)
{
    const int oh = blockIdx.x;   // 0..55
    const int b  = blockIdx.y;   // 0..63
    const int co = threadIdx.x;  // 0..191
    __shared__ float s_in[3*4*224];   // input strip: 4 rows x 3 ch

    for (int i = co; i < 3*4*224; i += 192) {
        int ci = i / (4*224);
        int r  = (i / 224) & 3;
        int c  = i % 224;
        s_in[i] = x[(((size_t)b*3 + ci)*224 + (oh*4 + r))*224 + c];
    }
    float wreg[48];
    #pragma unroll
    for (int k = 0; k < 48; ++k) wreg[k] = w[co*48 + k];   // contiguous per thread, L1-hot
    const float inv  = bg[co] * rsqrtf(bv[co] + EPS);
    const float beta = bb[co] - bm[co]*inv;
    __syncthreads();

    float* outp = &g_bufA[(((size_t)b*192 + co)*56 + oh)*56];
    for (int ow = 0; ow < 56; ++ow) {
        float acc = 0.f;
        #pragma unroll
        for (int ci = 0; ci < 3; ++ci)
            #pragma unroll
            for (int r = 0; r < 4; ++r)
                #pragma unroll
                for (int c = 0; c < 4; ++c)
                    acc = fmaf(wreg[(ci*4+r)*4+c], s_in[(ci*4+r)*224 + ow*4 + c], acc);
        outp[ow] = gelu_exact(acc*inv + beta);
    }
}

// ---------------------------------------------------------------------------
// region conv: per-tile 3x3 SAME conv (192->192) + per-tile BN + GELU + residual,
// IN PLACE on buf. Tile is always 7x7 (56/8 and 28/4). block=(b, tile g),
// 192 threads = c_out. Input tile staged fully in smem -> in-place is safe.
// Register-blocked: 49 accumulators, 49-reg input plane per c_in, 361 FMAs/c_in.
// ---------------------------------------------------------------------------
__global__ __launch_bounds__(192) void region_kernel(
    const float* __restrict__ w,
    const float* __restrict__ bg, const float* __restrict__ bb,
    const float* __restrict__ bm, const float* __restrict__ bv,
    int H)   // 56 (grid 8x8) or 28 (grid 4x4)
{
    float* buf = (H == 56) ? g_bufA : g_bufB;
    const int GW = H / 7;
    const int b  = blockIdx.x;
    const int g  = blockIdx.y;
    const int co = threadIdx.x;
    const int base_h = (g / GW) * 7;
    const int base_w = (g % GW) * 7;

    __shared__ float s_in[192*49];   // 37.6 KB
    for (int i = co; i < 192*49; i += 192) {
        int ci = i / 49, p = i % 49;
        s_in[i] = buf[(((size_t)b*192 + ci)*H + base_h + p/7)*H + base_w + p%7];
    }
    __syncthreads();

    float acc[49];
    #pragma unroll
    for (int j = 0; j < 49; ++j) acc[j] = 0.f;

    const float* wbase = w + (((size_t)g*192 + co)*192)*9;  // thread streams contiguous 6.9KB
    for (int ci = 0; ci < 192; ++ci) {
        float in[49];
        #pragma unroll
        for (int j = 0; j < 49; ++j) in[j] = s_in[ci*49 + j];   // broadcast LDS
        float wv[9];
        #pragma unroll
        for (int k = 0; k < 9; ++k) wv[k] = wbase[ci*9 + k];
        #pragma unroll
        for (int ky = 0; ky < 3; ++ky)
        #pragma unroll
        for (int kx = 0; kx < 3; ++kx) {
            const float wk = wv[ky*3+kx];
            #pragma unroll
            for (int oh = 0; oh < 7; ++oh) {
                const int ih = oh + ky - 1;
                if (ih < 0 || ih > 6) continue;   // compile-time pruned (SAME padding)
                #pragma unroll
                for (int ow = 0; ow < 7; ++ow) {
                    const int iw = ow + kx - 1;
                    if (iw < 0 || iw > 6) continue;
                    acc[oh*7+ow] = fmaf(wk, in[ih*7+iw], acc[oh*7+ow]);
                }
            }
        }
    }

    const int gc = g*192 + co;
    const float inv  = bg[gc] * rsqrtf(bv[gc] + EPS);
    const float beta = bb[gc] - bm[gc]*inv;
    #pragma unroll
    for (int j = 0; j < 49; ++j) {
        float y = gelu_exact(acc[j]*inv + beta) + s_in[co*49 + j];   // residual
        buf[(((size_t)b*192 + co)*H + base_h + j/7)*H + base_w + j%7] = y;
    }
}

// ---------------------------------------------------------------------------
// conv2: bufA(64,192,56,56) * w(192,192,2,2) stride2 -> bn -> gelu -> bufB(64,192,28,28)
// block = (q half-row, oh, b); 192 threads = c_out; 14 outputs/thread in registers.
// ---------------------------------------------------------------------------
__global__ __launch_bounds__(192) void conv2_kernel(
    const float* __restrict__ w,
    const float* __restrict__ bg, const float* __restrict__ bb,
    const float* __restrict__ bm, const float* __restrict__ bv)
{
    const int q  = blockIdx.x;   // 0..1  (ow in [14q, 14q+14))
    const int oh = blockIdx.y;   // 0..27
    const int b  = blockIdx.z;   // 0..63
    const int co = threadIdx.x;  // 0..191
    __shared__ float s_in[192*2*28];   // 43 KB

    for (int i = co; i < 192*2*28; i += 192) {
        int ci = i / 56, r = (i/28) & 1, c = i % 28;
        s_in[i] = g_bufA[(((size_t)b*192 + ci)*56 + 2*oh + r)*56 + q*28 + c];
    }
    __syncthreads();

    float acc[14];
    #pragma unroll
    for (int j = 0; j < 14; ++j) acc[j] = 0.f;

    const float* wp = w + (size_t)co*192*4;
    for (int ci = 0; ci < 192; ++ci) {
        const float w0 = wp[ci*4+0], w1 = wp[ci*4+1], w2 = wp[ci*4+2], w3 = wp[ci*4+3];
        const float* r0 = &s_in[ci*56];
        const float* r1 = &s_in[ci*56 + 28];
        #pragma unroll
        for (int ow = 0; ow < 14; ++ow) {
            acc[ow] = fmaf(w0, r0[2*ow],   acc[ow]);
            acc[ow] = fmaf(w1, r0[2*ow+1], acc[ow]);
            acc[ow] = fmaf(w2, r1[2*ow],   acc[ow]);
            acc[ow] = fmaf(w3, r1[2*ow+1], acc[ow]);
        }
    }
    const float inv  = bg[co] * rsqrtf(bv[co] + EPS);
    const float beta = bb[co] - bm[co]*inv;
    float* op = &g_bufB[(((size_t)b*192 + co)*28 + oh)*28 + q*14];
    #pragma unroll
    for (int ow = 0; ow < 14; ++ow) op[ow] = gelu_exact(acc[ow]*inv + beta);
}

// ---------------------------------------------------------------------------
// conv3: bufB(64,192,28,28) * w(768,192,2,2) stride2 -> bn -> transpose write
// out[b, oh*14+ow, co]  (B,196,768). block=(oh,b), 768 threads = c_out.
// ---------------------------------------------------------------------------
__global__ __launch_bounds__(768) void conv3_kernel(
    const float* __restrict__ w,
    const float* __restrict__ bg, const float* __restrict__ bb,
    const float* __restrict__ bm, const float* __restrict__ bv,
    float* __restrict__ out)
{
    const int oh = blockIdx.x;   // 0..13
    const int b  = blockIdx.y;   // 0..63
    const int co = threadIdx.x;  // 0..767
    __shared__ float s_in[192*2*28];   // 43 KB

    for (int i = co; i < 192*2*28; i += 768) {
        int ci = i / 56, r = (i/28) & 1, c = i % 28;
        s_in[i] = g_bufB[(((size_t)b*192 + ci)*28 + 2*oh + r)*28 + c];
    }
    __syncthreads();

    float acc[14];
    #pragma unroll
    for (int j = 0; j < 14; ++j) acc[j] = 0.f;

    const float* wp = w + (size_t)co*192*4;
    for (int ci = 0; ci < 192; ++ci) {
        const float w0 = wp[ci*4+0], w1 = wp[ci*4+1], w2 = wp[ci*4+2], w3 = wp[ci*4+3];
        const float* r0 = &s_in[ci*56];
        const float* r1 = &s_in[ci*56 + 28];
        #pragma unroll
        for (int ow = 0; ow < 14; ++ow) {
            acc[ow] = fmaf(w0, r0[2*ow],   acc[ow]);
            acc[ow] = fmaf(w1, r0[2*ow+1], acc[ow]);
            acc[ow] = fmaf(w2, r1[2*ow],   acc[ow]);
            acc[ow] = fmaf(w3, r1[2*ow+1], acc[ow]);
        }
    }
    const float inv  = bg[co] * rsqrtf(bv[co] + EPS);
    const float beta = bb[co] - bm[co]*inv;
    #pragma unroll
    for (int ow = 0; ow < 14; ++ow)
        out[((size_t)b*196 + oh*14 + ow)*768 + co] = acc[ow]*inv + beta;   // coalesced over co
}

// ---------------------------------------------------------------------------
// Input order (metadata): 0 x, 1 conv1_w, 2-5 bn1(g,b,m,v), 6 r1_w, 7-10 r1(g,b,m,v),
// 11 conv2_w, 12-15 bn2, 16 r2_w, 17-20 r2, 21 conv3_w, 22-25 bn3
// ---------------------------------------------------------------------------
extern "C" void kernel_launch(void* const* d_in, const int* in_sizes, int n_in,
                              void* d_out, int out_size)
{
    const float* x       = (const float*)d_in[0];
    const float* c1w     = (const float*)d_in[1];
    const float* b1g = (const float*)d_in[2],  *b1b = (const float*)d_in[3];
    const float* b1m = (const float*)d_in[4],  *b1v = (const float*)d_in[5];
    const float* r1w     = (const float*)d_in[6];
    const float* r1g = (const float*)d_in[7],  *r1b = (const float*)d_in[8];
    const float* r1m = (const float*)d_in[9],  *r1v = (const float*)d_in[10];
    const float* c2w     = (const float*)d_in[11];
    const float* b2g = (const float*)d_in[12], *b2b = (const float*)d_in[13];
    const float* b2m = (const float*)d_in[14], *b2v = (const float*)d_in[15];
    const float* r2w     = (const float*)d_in[16];
    const float* r2g = (const float*)d_in[17], *r2b = (const float*)d_in[18];
    const float* r2m = (const float*)d_in[19], *r2v = (const float*)d_in[20];
    const float* c3w     = (const float*)d_in[21];
    const float* b3g = (const float*)d_in[22], *b3b = (const float*)d_in[23];
    const float* b3m = (const float*)d_in[24], *b3v = (const float*)d_in[25];
    float* out = (float*)d_out;

    conv1_kernel<<<dim3(56, 64), 192>>>(x, c1w, b1g, b1b, b1m, b1v);
    region_kernel<<<dim3(64, 64), 192>>>(r1w, r1g, r1b, r1m, r1v, 56);
    conv2_kernel<<<dim3(2, 28, 64), 192>>>(c2w, b2g, b2b, b2m, b2v);
    region_kernel<<<dim3(64, 16), 192>>>(r2w, r2g, r2b, r2m, r2v, 28);
    conv3_kernel<<<dim3(14, 64), 768>>>(c3w, b3g, b3b, b3m, b3v, out);
}

// round 3
// speedup vs baseline: 2.4693x; 2.4693x over previous
#include <cuda_runtime.h>
#include <math.h>

#define EPS 1e-5f

// Scratch (device globals — no runtime allocation)
__device__ float g_bufA[(size_t)64*192*56*56];     // 154 MB: conv1 out, region1 in-place
__device__ float g_bufB[(size_t)64*192*28*28];     // 38.5 MB: conv2 out, region2 in-place
__device__ float g_r1wT[(size_t)64*192*9*192];     // 85 MB: r1 weights [g][ci][k][co]
__device__ float g_r2wT[(size_t)16*192*9*192];     // 21 MB: r2 weights [g][ci][k][co]
__device__ float g_c2wT[(size_t)192*192*4];        // conv2 weights [ci][co][k]
__device__ float g_c3wT[(size_t)192*768*4];        // conv3 weights [ci][co][k]

__device__ __forceinline__ float gelu_exact(float x) {
    return 0.5f * x * (1.0f + erff(x * 0.70710678118654752f));
}

// ---------------------------------------------------------------------------
// Weight transposes (coalesced writes; reads L1/L2-served, one-shot streams)
// ---------------------------------------------------------------------------
__global__ void transpose_region_w(const float* __restrict__ w, float* __restrict__ wT, int total)
{
    int idx = blockIdx.x * blockDim.x + threadIdx.x;
    if (idx >= total) return;
    int co = idx % 192;
    int t  = idx / 192;
    int k  = t % 9;  t /= 9;
    int ci = t % 192;
    int g  = t / 192;
    wT[idx] = w[(((size_t)g*192 + co)*192 + ci)*9 + k];
}

__global__ void transpose_conv_w(const float* __restrict__ w, float* __restrict__ wT, int CO, int total)
{
    int idx = blockIdx.x * blockDim.x + threadIdx.x;
    if (idx >= total) return;
    int k  = idx & 3;
    int t  = idx >> 2;
    int co = t % CO;
    int ci = t / CO;
    wT[idx] = w[(((size_t)co*192) + ci)*4 + k];
}

// ---------------------------------------------------------------------------
// conv1: x(64,3,224,224) * w(192,3,4,4) stride4 VALID -> bn -> gelu -> bufA
// ---------------------------------------------------------------------------
__global__ __launch_bounds__(192) void conv1_kernel(
    const float* __restrict__ x, const float* __restrict__ w,
    const float* __restrict__ bg, const float* __restrict__ bb,
    const float* __restrict__ bm, const float* __restrict__ bv)
{
    const int oh = blockIdx.x;
    const int b  = blockIdx.y;
    const int co = threadIdx.x;
    __shared__ float s_in[3*4*224];

    for (int i = co; i < 3*4*224; i += 192) {
        int ci = i / (4*224);
        int r  = (i / 224) & 3;
        int c  = i % 224;
        s_in[i] = x[(((size_t)b*3 + ci)*224 + (oh*4 + r))*224 + c];
    }
    float wreg[48];
    #pragma unroll
    for (int k = 0; k < 48; ++k) wreg[k] = w[co*48 + k];
    const float inv  = bg[co] * rsqrtf(bv[co] + EPS);
    const float beta = bb[co] - bm[co]*inv;
    __syncthreads();

    float* outp = &g_bufA[(((size_t)b*192 + co)*56 + oh)*56];
    for (int ow = 0; ow < 56; ++ow) {
        float acc = 0.f;
        #pragma unroll
        for (int ci = 0; ci < 3; ++ci)
            #pragma unroll
            for (int r = 0; r < 4; ++r)
                #pragma unroll
                for (int c = 0; c < 4; ++c)
                    acc = fmaf(wreg[(ci*4+r)*4+c], s_in[(ci*4+r)*224 + ow*4 + c], acc);
        outp[ow] = gelu_exact(acc*inv + beta);
    }
}

// ---------------------------------------------------------------------------
// region conv: per-tile 3x3 SAME (192->192) + BN + GELU + residual, IN PLACE.
// Weights from transposed layout [g][ci][k][co] -> lane-coalesced LDG.
// Input plane in smem padded to 52 floats -> LDS.128 broadcast reads.
// ---------------------------------------------------------------------------
__global__ __launch_bounds__(192, 2) void region_kernel(
    const float* __restrict__ wT,
    const float* __restrict__ bg, const float* __restrict__ bb,
    const float* __restrict__ bm, const float* __restrict__ bv,
    int H)   // 56 (grid 8x8, uses g_r1wT caller) or 28 (grid 4x4)
{
    float* buf = (H == 56) ? g_bufA : g_bufB;
    const int GW = H / 7;
    const int b  = blockIdx.x;
    const int g  = blockIdx.y;
    const int co = threadIdx.x;
    const int base_h = (g / GW) * 7;
    const int base_w = (g % GW) * 7;

    __shared__ float s_in[192*52];   // plane stride 52 (16B-aligned), 39.9 KB
    const float* src = buf + (size_t)b*192*H*H;
    for (int i = co; i < 192*49; i += 192) {
        int ci = i / 49, p = i % 49;
        s_in[ci*52 + p] = src[((size_t)ci*H + base_h + p/7)*H + base_w + p%7];
    }
    __syncthreads();

    float acc[49];
    #pragma unroll
    for (int j = 0; j < 49; ++j) acc[j] = 0.f;

    const float* wp = wT + (size_t)g*192*9*192 + co;   // + (ci*9+k)*192
    for (int ci = 0; ci < 192; ++ci) {
        float wv[9];
        #pragma unroll
        for (int k = 0; k < 9; ++k) wv[k] = wp[(ci*9 + k)*192];   // lane-contiguous LDG

        float in[52];
        const float4* sp = reinterpret_cast<const float4*>(&s_in[ci*52]);
        #pragma unroll
        for (int q = 0; q < 13; ++q) {
            float4 v = sp[q];                                      // broadcast LDS.128
            in[4*q] = v.x; in[4*q+1] = v.y; in[4*q+2] = v.z; in[4*q+3] = v.w;
        }

        #pragma unroll
        for (int ky = 0; ky < 3; ++ky)
        #pragma unroll
        for (int kx = 0; kx < 3; ++kx) {
            const float wk = wv[ky*3+kx];
            #pragma unroll
            for (int oh = 0; oh < 7; ++oh) {
                const int ih = oh + ky - 1;
                if (ih < 0 || ih > 6) continue;       // compile-time pruned
                #pragma unroll
                for (int ow = 0; ow < 7; ++ow) {
                    const int iw = ow + kx - 1;
                    if (iw < 0 || iw > 6) continue;
                    acc[oh*7+ow] = fmaf(wk, in[ih*7+iw], acc[oh*7+ow]);
                }
            }
        }
    }

    const int gc = g*192 + co;
    const float inv  = bg[gc] * rsqrtf(bv[gc] + EPS);
    const float beta = bb[gc] - bm[gc]*inv;
    float* dst = buf + (size_t)b*192*H*H;
    #pragma unroll
    for (int j = 0; j < 49; ++j) {
        float y = gelu_exact(acc[j]*inv + beta) + s_in[co*52 + j];   // residual
        dst[((size_t)co*H + base_h + j/7)*H + base_w + j%7] = y;
    }
}

// ---------------------------------------------------------------------------
// conv2: bufA * wT2[ci][co][k] stride2 -> bn -> gelu -> bufB. float4 smem reads.
// ---------------------------------------------------------------------------
__global__ __launch_bounds__(192) void conv2_kernel(
    const float* __restrict__ wT,
    const float* __restrict__ bg, const float* __restrict__ bb,
    const float* __restrict__ bm, const float* __restrict__ bv)
{
    const int q  = blockIdx.x;   // 0..1
    const int oh = blockIdx.y;   // 0..27
    const int b  = blockIdx.z;   // 0..63
    const int co = threadIdx.x;  // 0..191
    __shared__ float s_in[192*2*28];   // 43 KB, row stride 28 floats (16B-aligned pairs: 56/row-pair)

    for (int i = co; i < 192*2*28; i += 192) {
        int ci = i / 56, r = (i/28) & 1, c = i % 28;
        s_in[i] = g_bufA[(((size_t)b*192 + ci)*56 + 2*oh + r)*56 + q*28 + c];
    }
    __syncthreads();

    float acc[14];
    #pragma unroll
    for (int j = 0; j < 14; ++j) acc[j] = 0.f;

    const float4* w4 = reinterpret_cast<const float4*>(wT) + co;   // + ci*192
    for (int ci = 0; ci < 192; ++ci) {
        const float4 wv = w4[ci*192];                              // lane-contiguous LDG.128
        const float4* r0 = reinterpret_cast<const float4*>(&s_in[ci*56]);
        const float4* r1 = reinterpret_cast<const float4*>(&s_in[ci*56 + 28]);
        #pragma unroll
        for (int p = 0; p < 7; ++p) {
            float4 a = r0[p], c = r1[p];                           // broadcast LDS.128
            acc[2*p]   = fmaf(wv.x, a.x, fmaf(wv.y, a.y, fmaf(wv.z, c.x, fmaf(wv.w, c.y, acc[2*p]))));
            acc[2*p+1] = fmaf(wv.x, a.z, fmaf(wv.y, a.w, fmaf(wv.z, c.z, fmaf(wv.w, c.w, acc[2*p+1]))));
        }
    }
    const float inv  = bg[co] * rsqrtf(bv[co] + EPS);
    const float beta = bb[co] - bm[co]*inv;
    float* op = &g_bufB[(((size_t)b*192 + co)*28 + oh)*28 + q*14];
    #pragma unroll
    for (int ow = 0; ow < 14; ++ow) op[ow] = gelu_exact(acc[ow]*inv + beta);
}

// ---------------------------------------------------------------------------
// conv3: bufB * wT3[ci][co][k] stride2 -> bn -> transposed write (B,196,768)
// ---------------------------------------------------------------------------
__global__ __launch_bounds__(768) void conv3_kernel(
    const float* __restrict__ wT,
    const float* __restrict__ bg, const float* __restrict__ bb,
    const float* __restrict__ bm, const float* __restrict__ bv,
    float* __restrict__ out)
{
    const int oh = blockIdx.x;   // 0..13
    const int b  = blockIdx.y;   // 0..63
    const int co = threadIdx.x;  // 0..767
    __shared__ float s_in[192*2*28];

    for (int i = co; i < 192*2*28; i += 768) {
        int ci = i / 56, r = (i/28) & 1, c = i % 28;
        s_in[i] = g_bufB[(((size_t)b*192 + ci)*28 + 2*oh + r)*28 + c];
    }
    __syncthreads();

    float acc[14];
    #pragma unroll
    for (int j = 0; j < 14; ++j) acc[j] = 0.f;

    const float4* w4 = reinterpret_cast<const float4*>(wT) + co;   // + ci*768
    for (int ci = 0; ci < 192; ++ci) {
        const float4 wv = w4[ci*768];
        const float4* r0 = reinterpret_cast<const float4*>(&s_in[ci*56]);
        const float4* r1 = reinterpret_cast<const float4*>(&s_in[ci*56 + 28]);
        #pragma unroll
        for (int p = 0; p < 7; ++p) {
            float4 a = r0[p], c = r1[p];
            acc[2*p]   = fmaf(wv.x, a.x, fmaf(wv.y, a.y, fmaf(wv.z, c.x, fmaf(wv.w, c.y, acc[2*p]))));
            acc[2*p+1] = fmaf(wv.x, a.z, fmaf(wv.y, a.w, fmaf(wv.z, c.z, fmaf(wv.w, c.w, acc[2*p+1]))));
        }
    }
    const float inv  = bg[co] * rsqrtf(bv[co] + EPS);
    const float beta = bb[co] - bm[co]*inv;
    #pragma unroll
    for (int ow = 0; ow < 14; ++ow)
        out[((size_t)b*196 + oh*14 + ow)*768 + co] = acc[ow]*inv + beta;
}

// ---------------------------------------------------------------------------
extern "C" void kernel_launch(void* const* d_in, const int* in_sizes, int n_in,
                              void* d_out, int out_size)
{
    const float* x       = (const float*)d_in[0];
    const float* c1w     = (const float*)d_in[1];
    const float* b1g = (const float*)d_in[2],  *b1b = (const float*)d_in[3];
    const float* b1m = (const float*)d_in[4],  *b1v = (const float*)d_in[5];
    const float* r1w     = (const float*)d_in[6];
    const float* r1g = (const float*)d_in[7],  *r1b = (const float*)d_in[8];
    const float* r1m = (const float*)d_in[9],  *r1v = (const float*)d_in[10];
    const float* c2w     = (const float*)d_in[11];
    const float* b2g = (const float*)d_in[12], *b2b = (const float*)d_in[13];
    const float* b2m = (const float*)d_in[14], *b2v = (const float*)d_in[15];
    const float* r2w     = (const float*)d_in[16];
    const float* r2g = (const float*)d_in[17], *r2b = (const float*)d_in[18];
    const float* r2m = (const float*)d_in[19], *r2v = (const float*)d_in[20];
    const float* c3w     = (const float*)d_in[21];
    const float* b3g = (const float*)d_in[22], *b3b = (const float*)d_in[23];
    const float* b3m = (const float*)d_in[24], *b3v = (const float*)d_in[25];
    float* out = (float*)d_out;

    float *r1wT, *r2wT, *c2wT, *c3wT;
    cudaGetSymbolAddress((void**)&r1wT, g_r1wT);
    cudaGetSymbolAddress((void**)&r2wT, g_r2wT);
    cudaGetSymbolAddress((void**)&c2wT, g_c2wT);
    cudaGetSymbolAddress((void**)&c3wT, g_c3wT);

    {   // weight transposes
        int t1 = 64*192*192*9;
        transpose_region_w<<<(t1 + 255)/256, 256>>>(r1w, r1wT, t1);
        int t2 = 16*192*192*9;
        transpose_region_w<<<(t2 + 255)/256, 256>>>(r2w, r2wT, t2);
        int t3 = 192*192*4;
        transpose_conv_w<<<(t3 + 255)/256, 256>>>(c2w, c2wT, 192, t3);
        int t4 = 192*768*4;
        transpose_conv_w<<<(t4 + 255)/256, 256>>>(c3w, c3wT, 768, t4);
    }

    conv1_kernel<<<dim3(56, 64), 192>>>(x, c1w, b1g, b1b, b1m, b1v);
    region_kernel<<<dim3(64, 64), 192>>>(r1wT, r1g, r1b, r1m, r1v, 56);
    conv2_kernel<<<dim3(2, 28, 64), 192>>>(c2wT, b2g, b2b, b2m, b2v);
    region_kernel<<<dim3(64, 16), 192>>>(r2wT, r2g, r2b, r2m, r2v, 28);
    conv3_kernel<<<dim3(14, 64), 768>>>(c3wT, b3g, b3b, b3m, b3v, out);
}